// round 2
// baseline (speedup 1.0000x reference)
#include <cuda_runtime.h>
#include <cuda_bf16.h>
#include <cstdint>
#include <cstddef>

// ---------------------------------------------------------------------------
// QLSTM  T=512 B=64 D=512 H=512
//  z_t = x_t@Wx + b4 + h_t@(Wh+R)
//  Phase A (prep):   split X and weights into bf16 hi/lo, permute columns
//  Phase B (gemm):   Z0[32768,2048] = X@Wx + b4   (3-product bf16 split)
//  Phase C (rnn):    persistent kernel, 512 steps, grid barrier per step
//  Column permutation: z column for (hidden hc, gate g) stored at n = hc*4+g
// ---------------------------------------------------------------------------

#define TT 512
#define BB 64
#define DD 512
#define HH 512
#define NCOLS 2048
#define MTOT (TT * BB)          // 32768
#define RNN_CTAS 64

// ------------------------- static device scratch ---------------------------
__device__ __align__(128) __nv_bfloat16 g_Ax[(size_t)MTOT * 1024];   // X split  [m][hi|lo]
__device__ __align__(128) __nv_bfloat16 g_Bx[(size_t)NCOLS * 1024];  // Wx split [n][hi|lo]
__device__ __align__(128) __nv_bfloat16 g_Br[(size_t)NCOLS * 1024];  // (Wh+R)   [n][hi|lo]
__device__ __align__(128) float g_b4[NCOLS];
__device__ __align__(128) float g_Z0[(size_t)MTOT * NCOLS];          // 256 MB
__device__ __align__(128) __nv_bfloat16 g_hbuf[2 * BB * 1024];       // h split ping-pong
__device__ unsigned g_cnt;
__device__ volatile unsigned g_gen;

// ------------------------------ helpers ------------------------------------
__device__ __forceinline__ uint32_t smem_u32(const void* p) {
    return (uint32_t)__cvta_generic_to_shared(p);
}
__device__ __forceinline__ void ldsm_x4(uint32_t& r0, uint32_t& r1, uint32_t& r2,
                                        uint32_t& r3, uint32_t addr) {
    asm volatile("ldmatrix.sync.aligned.m8n8.x4.shared.b16 {%0,%1,%2,%3},[%4];\n"
                 : "=r"(r0), "=r"(r1), "=r"(r2), "=r"(r3) : "r"(addr));
}
__device__ __forceinline__ void ldsm_x2(uint32_t& r0, uint32_t& r1, uint32_t addr) {
    asm volatile("ldmatrix.sync.aligned.m8n8.x2.shared.b16 {%0,%1},[%2];\n"
                 : "=r"(r0), "=r"(r1) : "r"(addr));
}
__device__ __forceinline__ void mma16816(float* d, const uint32_t* a,
                                         uint32_t b0, uint32_t b1) {
    asm volatile(
        "mma.sync.aligned.m16n8k16.row.col.f32.bf16.bf16.f32 "
        "{%0,%1,%2,%3},{%4,%5,%6,%7},{%8,%9},{%0,%1,%2,%3};\n"
        : "+f"(d[0]), "+f"(d[1]), "+f"(d[2]), "+f"(d[3])
        : "r"(a[0]), "r"(a[1]), "r"(a[2]), "r"(a[3]), "r"(b0), "r"(b1));
}
__device__ __forceinline__ void cp16(void* s, const void* g) {
    asm volatile("cp.async.cg.shared.global [%0],[%1],16;\n"
                 :: "r"(smem_u32(s)), "l"(g));
}
__device__ __forceinline__ void cp_commit() {
    asm volatile("cp.async.commit_group;\n");
}
__device__ __forceinline__ float sigf(float x) { return 1.f / (1.f + __expf(-x)); }
__device__ __forceinline__ float tanhfast(float x) {
    return 2.f / (1.f + __expf(-2.f * x)) - 1.f;
}

__device__ __forceinline__ void grid_barrier() {
    __syncthreads();
    if (threadIdx.x == 0) {
        __threadfence();
        unsigned gen = g_gen;
        if (atomicAdd(&g_cnt, 1u) == gridDim.x - 1) {
            g_cnt = 0;
            __threadfence();
            g_gen = gen + 1;
        } else {
            while (g_gen == gen) __nanosleep(32);
        }
        __threadfence();
    }
    __syncthreads();
}

// ------------------------------- prep X ------------------------------------
__global__ void k_prep_x(const float* __restrict__ x) {
    size_t stride = (size_t)gridDim.x * blockDim.x;
    for (size_t i = (size_t)blockIdx.x * blockDim.x + threadIdx.x;
         i < (size_t)MTOT * 512; i += stride) {
        size_t m = i >> 9, k = i & 511;
        float v = x[i];
        __nv_bfloat16 hi = __float2bfloat16(v);
        float r = v - __bfloat162float(hi);
        g_Ax[m * 1024 + k] = hi;
        g_Ax[m * 1024 + 512 + k] = __float2bfloat16(r);
    }
}

// ------------------------------- prep W ------------------------------------
__global__ void k_prep_w(const float* __restrict__ Wf, const float* __restrict__ bf,
                         const float* __restrict__ Wi, const float* __restrict__ bi,
                         const float* __restrict__ Wg, const float* __restrict__ bg,
                         const float* __restrict__ Wo, const float* __restrict__ bo,
                         const float* __restrict__ Rf, const float* __restrict__ Ri,
                         const float* __restrict__ Rg, const float* __restrict__ Ro) {
    int n = blockIdx.x;          // permuted column 0..2047
    int g = n & 3, hc = n >> 2;
    const float* W = (g == 0) ? Wf : (g == 1) ? Wi : (g == 2) ? Wg : Wo;
    const float* R = (g == 0) ? Rf : (g == 1) ? Ri : (g == 2) ? Rg : Ro;
    const float* bb = (g == 0) ? bf : (g == 1) ? bi : (g == 2) ? bg : bo;

    for (int k = threadIdx.x; k < 512; k += blockDim.x) {
        float wx = W[(size_t)k * 512 + hc];
        __nv_bfloat16 hi = __float2bfloat16(wx);
        g_Bx[(size_t)n * 1024 + k] = hi;
        g_Bx[(size_t)n * 1024 + 512 + k] =
            __float2bfloat16(wx - __bfloat162float(hi));

        float wh = W[(size_t)(512 + k) * 512 + hc] + R[(size_t)k * 512 + hc];
        __nv_bfloat16 hih = __float2bfloat16(wh);
        g_Br[(size_t)n * 1024 + k] = hih;
        g_Br[(size_t)n * 1024 + 512 + k] =
            __float2bfloat16(wh - __bfloat162float(hih));
    }
    if (threadIdx.x == 0) g_b4[n] = bb[hc];

    int gt = blockIdx.x * blockDim.x + threadIdx.x;
    if (gt < 2 * BB * 1024) g_hbuf[gt] = __float2bfloat16(0.f);  // h0 = 0
    if (gt == 0) { g_cnt = 0; g_gen = 0; }
}

// --------------------------- phase B: Z0 GEMM ------------------------------
// CTA tile 128x64, 8 warps (4x2), warp tile 32x32. K chunks of 64, dbl-buffered.
#define P1_SA (128 * 72)
#define P1_SB (64 * 72)
#define P1_SMEM ((2 * P1_SA + 2 * P1_SB) * 2)

__global__ void __launch_bounds__(256) k_gemm_x() {
    extern __shared__ __nv_bfloat16 smp[];
    __nv_bfloat16* sA = smp;                // [2][128*72]
    __nv_bfloat16* sB = smp + 2 * P1_SA;    // [2][64*72]
    const int m0 = blockIdx.x * 128, n0 = blockIdx.y * 64;
    const int tid = threadIdx.x, lane = tid & 31, w = tid >> 5;
    const int wm = w & 3, wn = w >> 2;
    const int tg = lane >> 2, t4 = lane & 3;

    float acc[2][4][4];
#pragma unroll
    for (int jt = 0; jt < 4; jt++) {
        int col = n0 + wn * 32 + jt * 8 + 2 * t4;
        float b0 = g_b4[col], b1 = g_b4[col + 1];
#pragma unroll
        for (int mt = 0; mt < 2; mt++) {
            acc[mt][jt][0] = b0; acc[mt][jt][1] = b1;
            acc[mt][jt][2] = b0; acc[mt][jt][3] = b1;
        }
    }

    auto issue = [&](int cc, int buf) {
        int seg = cc >> 3, kb = (cc & 7) * 64;
        int aoff = (seg == 1) ? 512 : 0, boff = (seg == 2) ? 512 : 0;
        size_t abase = (size_t)m0 * 1024 + aoff + kb;
        for (int u = tid; u < 1024; u += 256) {
            int r = u >> 3, c8 = (u & 7) * 8;
            cp16(&sA[buf * P1_SA + r * 72 + c8], &g_Ax[abase + (size_t)r * 1024 + c8]);
        }
        size_t bbase = (size_t)n0 * 1024 + boff + kb;
        for (int u = tid; u < 512; u += 256) {
            int r = u >> 3, c8 = (u & 7) * 8;
            cp16(&sB[buf * P1_SB + r * 72 + c8], &g_Bx[bbase + (size_t)r * 1024 + c8]);
        }
        cp_commit();
    };

    issue(0, 0);
    for (int cc = 0; cc < 24; cc++) {
        int buf = cc & 1;
        if (cc < 23) {
            issue(cc + 1, buf ^ 1);
            asm volatile("cp.async.wait_group 1;\n");
        } else {
            asm volatile("cp.async.wait_group 0;\n");
        }
        __syncthreads();
#pragma unroll
        for (int kk = 0; kk < 4; kk++) {
            int ko = kk * 16;
            uint32_t a[2][4];
#pragma unroll
            for (int mt = 0; mt < 2; mt++) {
                int row = wm * 32 + mt * 16 + (lane & 15);
                int kx = ko + ((lane >> 4) << 3);
                ldsm_x4(a[mt][0], a[mt][1], a[mt][2], a[mt][3],
                        smem_u32(&sA[buf * P1_SA + row * 72 + kx]));
            }
#pragma unroll
            for (int jt = 0; jt < 4; jt++) {
                int nr = wn * 32 + jt * 8 + (lane & 7);
                int kx = ko + (((lane >> 3) & 1) << 3);
                uint32_t b0, b1;
                ldsm_x2(b0, b1, smem_u32(&sB[buf * P1_SB + nr * 72 + kx]));
                mma16816(acc[0][jt], a[0], b0, b1);
                mma16816(acc[1][jt], a[1], b0, b1);
            }
        }
        __syncthreads();
    }

#pragma unroll
    for (int mt = 0; mt < 2; mt++) {
        int row = m0 + wm * 32 + mt * 16 + tg;
#pragma unroll
        for (int jt = 0; jt < 4; jt++) {
            int col = n0 + wn * 32 + jt * 8 + 2 * t4;
            *(float2*)&g_Z0[(size_t)row * 2048 + col] =
                make_float2(acc[mt][jt][0], acc[mt][jt][1]);
            *(float2*)&g_Z0[(size_t)(row + 8) * 2048 + col] =
                make_float2(acc[mt][jt][2], acc[mt][jt][3]);
        }
    }
}

// --------------------------- phase C: recurrence ---------------------------
// 64 CTAs x 256 thr. CTA j owns permuted cols [32j,32j+32) = hidden [8j,8j+8).
// SMEM: weight slice 32x1032 + h-split A 64x1032 + 512-float h staging tile.
#define ST2 1032
#define P2_WB (32 * ST2)
#define P2_AB (64 * ST2)
#define P2_SMEM ((P2_WB + P2_AB) * 2 + 512 * 4)
#define HX_OFF ((size_t)TT * BB * HH)

__global__ void __launch_bounds__(256) k_rnn(float* __restrict__ out, int out_size) {
    extern __shared__ __nv_bfloat16 smp[];
    __nv_bfloat16* sB = smp;            // 32*1032
    __nv_bfloat16* sA = smp + P2_WB;    // 64*1032
    float* sH = (float*)(smp + P2_WB + P2_AB);  // [64][8]
    const int j = blockIdx.x, n0 = j * 32;
    const int tid = threadIdx.x, lane = tid & 31, w = tid >> 5;
    const int wm = w & 3, wn = w >> 2;
    const int tg = lane >> 2, t4 = lane & 3;
    const bool ev = (t4 & 1) == 0;

    // resident weight slice for all 512 steps
    for (int u = tid; u < 32 * 128; u += 256) {
        int r = u >> 7, c8 = (u & 127) * 8;
        *(uint4*)&sB[r * ST2 + c8] = *(const uint4*)&g_Br[(size_t)(n0 + r) * 1024 + c8];
    }
    float cst[2][2] = {{0.f, 0.f}, {0.f, 0.f}};

    for (int t = 0; t < 512; t++) {
        int buf = t & 1;
        // load h split (64x1024 bf16) into SMEM
        for (int u = tid; u < 64 * 128; u += 256) {
            int r = u >> 7, c8 = (u & 127) * 8;
            cp16(&sA[r * ST2 + c8], &g_hbuf[buf * 65536 + r * 1024 + c8]);
        }
        cp_commit();

        // accumulator init = Z0 (bias folded in already)
        float acc[2][4];
        int zrow = t * 64 + wm * 16 + tg;
#pragma unroll
        for (int jt = 0; jt < 2; jt++) {
            int col = n0 + wn * 16 + jt * 8 + 2 * t4;
            float2 v0 = *(const float2*)&g_Z0[(size_t)zrow * 2048 + col];
            float2 v1 = *(const float2*)&g_Z0[(size_t)(zrow + 8) * 2048 + col];
            acc[jt][0] = v0.x; acc[jt][1] = v0.y;
            acc[jt][2] = v1.x; acc[jt][3] = v1.y;
        }
        asm volatile("cp.async.wait_group 0;\n");
        __syncthreads();

        // GEMM: M=64 N=32 K'=1536 (3 split segments)
#pragma unroll
        for (int seg = 0; seg < 3; seg++) {
            int aoff = (seg == 1) ? 512 : 0, boff = (seg == 2) ? 512 : 0;
#pragma unroll 4
            for (int kk = 0; kk < 32; kk++) {
                int ko = kk * 16;
                int row = wm * 16 + (lane & 15);
                int kx = aoff + ko + ((lane >> 4) << 3);
                uint32_t a[4];
                ldsm_x4(a[0], a[1], a[2], a[3], smem_u32(&sA[row * ST2 + kx]));
#pragma unroll
                for (int jt = 0; jt < 2; jt++) {
                    int nr = wn * 16 + jt * 8 + (lane & 7);
                    int kx2 = boff + ko + (((lane >> 3) & 1) << 3);
                    uint32_t b0, b1;
                    ldsm_x2(b0, b1, smem_u32(&sB[nr * ST2 + kx2]));
                    mma16816(acc[jt], a, b0, b1);
                }
            }
        }

        // gates: even lane has (f,i), odd has (g,o) for same (rows, hc)
        int nb = (t + 1) & 1;
#pragma unroll
        for (int jt = 0; jt < 2; jt++) {
            float r0 = __shfl_xor_sync(0xffffffffu, acc[jt][0], 1);
            float r1 = __shfl_xor_sync(0xffffffffu, acc[jt][1], 1);
            float r2 = __shfl_xor_sync(0xffffffffu, acc[jt][2], 1);
            float r3 = __shfl_xor_sync(0xffffffffu, acc[jt][3], 1);
            float zf0 = ev ? acc[jt][0] : r0, zi0 = ev ? acc[jt][1] : r1;
            float zg0 = ev ? r0 : acc[jt][0], zo0 = ev ? r1 : acc[jt][1];
            float zf1 = ev ? acc[jt][2] : r2, zi1 = ev ? acc[jt][3] : r3;
            float zg1 = ev ? r2 : acc[jt][2], zo1 = ev ? r3 : acc[jt][3];

            float c0 = sigf(zf0) * cst[jt][0] + sigf(zi0) * tanhfast(zg0);
            float c1 = sigf(zf1) * cst[jt][1] + sigf(zi1) * tanhfast(zg1);
            cst[jt][0] = c0; cst[jt][1] = c1;
            float h0 = sigf(zo0) * tanhfast(c0);
            float h1 = sigf(zo1) * tanhfast(c1);

            if (ev) {
                int b0r = wm * 16 + tg, b1r = b0r + 8;
                int hcl = 4 * wn + 2 * jt + (t4 >> 1);
                sH[b0r * 8 + hcl] = h0;
                sH[b1r * 8 + hcl] = h1;
                if (t == 511) {
                    int hcg = 8 * j + hcl;
                    if (HX_OFF + 32768 <= (size_t)out_size) {
                        out[HX_OFF + (size_t)b0r * 512 + hcg] = h0;
                        out[HX_OFF + (size_t)b1r * 512 + hcg] = h1;
                    }
                    if (HX_OFF + 65536 <= (size_t)out_size) {
                        out[HX_OFF + 32768 + (size_t)b0r * 512 + hcg] = c0;
                        out[HX_OFF + 32768 + (size_t)b1r * 512 + hcg] = c1;
                    }
                }
            }
        }
        __syncthreads();

        // coalesced h writes: out (fp32) + hi/lo split into next h buffer
        {
            int b = tid >> 2, hcl2 = (tid & 3) * 2;
            float2 hv = *(float2*)&sH[b * 8 + hcl2];
            *(float2*)&out[((size_t)t * 64 + b) * 512 + 8 * j + hcl2] = hv;
            __nv_bfloat16 hi0 = __float2bfloat16(hv.x);
            __nv_bfloat16 hi1 = __float2bfloat16(hv.y);
            __nv_bfloat16 lo0 = __float2bfloat16(hv.x - __bfloat162float(hi0));
            __nv_bfloat16 lo1 = __float2bfloat16(hv.y - __bfloat162float(hi1));
            __nv_bfloat162 hip; hip.x = hi0; hip.y = hi1;
            __nv_bfloat162 lop; lop.x = lo0; lop.y = lo1;
            *(__nv_bfloat162*)&g_hbuf[nb * 65536 + b * 1024 + 8 * j + hcl2] = hip;
            *(__nv_bfloat162*)&g_hbuf[nb * 65536 + b * 1024 + 512 + 8 * j + hcl2] = lop;
        }

        if (t < 511) grid_barrier();
    }
}

// ------------------------------- launch ------------------------------------
extern "C" void kernel_launch(void* const* d_in, const int* in_sizes, int n_in,
                              void* d_out, int out_size) {
    const float* x  = (const float*)d_in[0];
    const float* Wf = (const float*)d_in[1];
    const float* bf = (const float*)d_in[2];
    const float* Wi = (const float*)d_in[3];
    const float* bi = (const float*)d_in[4];
    const float* Wg = (const float*)d_in[5];
    const float* bg = (const float*)d_in[6];
    const float* Wo = (const float*)d_in[7];
    const float* bo = (const float*)d_in[8];
    const float* Rf = (const float*)d_in[9];
    const float* Ri = (const float*)d_in[10];
    const float* Rg = (const float*)d_in[11];
    const float* Ro = (const float*)d_in[12];

    cudaFuncSetAttribute(k_gemm_x, cudaFuncAttributeMaxDynamicSharedMemorySize, P1_SMEM);
    cudaFuncSetAttribute(k_rnn, cudaFuncAttributeMaxDynamicSharedMemorySize, P2_SMEM);

    k_prep_x<<<4096, 256>>>(x);
    k_prep_w<<<2048, 256>>>(Wf, bf, Wi, bi, Wg, bg, Wo, bo, Rf, Ri, Rg, Ro);
    k_gemm_x<<<dim3(256, 32), 256, P1_SMEM>>>();
    k_rnn<<<RNN_CTAS, 256, P2_SMEM>>>((float*)d_out, out_size);
}

// round 3
// speedup vs baseline: 1.2303x; 1.2303x over previous
#include <cuda_runtime.h>
#include <cuda_bf16.h>
#include <cstdint>
#include <cstddef>

// ---------------------------------------------------------------------------
// QLSTM  T=512 B=64 D=512 H=512
//  z_t = x_t@Wx + b4 + h_t@(Wh+R)
//  Phase A (prep):   split X and weights into bf16 hi/lo, permute columns
//  Phase B (gemm):   Z0[32768,2048] = X@Wx + b4   (3-product bf16 split)
//  Phase C (rnn):    persistent kernel, 128 CTAs x 16 cols, 512 steps,
//                    chunked h-load pipelined into mma, Z0 prefetched.
//  Column permutation: z column for (hidden hc, gate g) stored at n = hc*4+g
// ---------------------------------------------------------------------------

#define TT 512
#define BB 64
#define DD 512
#define HH 512
#define NCOLS 2048
#define MTOT (TT * BB)          // 32768
#define RNN_CTAS 128

// ------------------------- static device scratch ---------------------------
__device__ __align__(128) __nv_bfloat16 g_Ax[(size_t)MTOT * 1024];   // X split  [m][hi|lo]
__device__ __align__(128) __nv_bfloat16 g_Bx[(size_t)NCOLS * 1024];  // Wx split [n][hi|lo]
__device__ __align__(128) __nv_bfloat16 g_Br[(size_t)NCOLS * 1024];  // (Wh+R)   [n][hi|lo]
__device__ __align__(128) float g_b4[NCOLS];
__device__ __align__(128) float g_Z0[(size_t)MTOT * NCOLS];          // 256 MB
__device__ __align__(128) __nv_bfloat16 g_hbuf[2 * BB * 1024];       // h split ping-pong
__device__ unsigned g_cnt;
__device__ volatile unsigned g_gen;

// ------------------------------ helpers ------------------------------------
__device__ __forceinline__ uint32_t smem_u32(const void* p) {
    return (uint32_t)__cvta_generic_to_shared(p);
}
__device__ __forceinline__ void ldsm_x4(uint32_t& r0, uint32_t& r1, uint32_t& r2,
                                        uint32_t& r3, uint32_t addr) {
    asm volatile("ldmatrix.sync.aligned.m8n8.x4.shared.b16 {%0,%1,%2,%3},[%4];\n"
                 : "=r"(r0), "=r"(r1), "=r"(r2), "=r"(r3) : "r"(addr));
}
__device__ __forceinline__ void ldsm_x2(uint32_t& r0, uint32_t& r1, uint32_t addr) {
    asm volatile("ldmatrix.sync.aligned.m8n8.x2.shared.b16 {%0,%1},[%2];\n"
                 : "=r"(r0), "=r"(r1) : "r"(addr));
}
__device__ __forceinline__ void mma16816(float* d, const uint32_t* a,
                                         uint32_t b0, uint32_t b1) {
    asm volatile(
        "mma.sync.aligned.m16n8k16.row.col.f32.bf16.bf16.f32 "
        "{%0,%1,%2,%3},{%4,%5,%6,%7},{%8,%9},{%0,%1,%2,%3};\n"
        : "+f"(d[0]), "+f"(d[1]), "+f"(d[2]), "+f"(d[3])
        : "r"(a[0]), "r"(a[1]), "r"(a[2]), "r"(a[3]), "r"(b0), "r"(b1));
}
__device__ __forceinline__ void cp16(void* s, const void* g) {
    asm volatile("cp.async.cg.shared.global [%0],[%1],16;\n"
                 :: "r"(smem_u32(s)), "l"(g));
}
__device__ __forceinline__ void cp_commit() {
    asm volatile("cp.async.commit_group;\n");
}
__device__ __forceinline__ float sigf(float x) { return 1.f / (1.f + __expf(-x)); }
__device__ __forceinline__ float tanhfast(float x) {
    return 2.f / (1.f + __expf(-2.f * x)) - 1.f;
}

__device__ __forceinline__ void grid_barrier() {
    __syncthreads();
    if (threadIdx.x == 0) {
        __threadfence();
        unsigned gen = g_gen;
        if (atomicAdd(&g_cnt, 1u) == gridDim.x - 1) {
            g_cnt = 0;
            __threadfence();
            g_gen = gen + 1;
        } else {
            while (g_gen == gen) __nanosleep(32);
        }
        __threadfence();
    }
    __syncthreads();
}

// ------------------------------- prep X ------------------------------------
__global__ void k_prep_x(const float* __restrict__ x) {
    size_t stride = (size_t)gridDim.x * blockDim.x;
    for (size_t i = (size_t)blockIdx.x * blockDim.x + threadIdx.x;
         i < (size_t)MTOT * 512; i += stride) {
        size_t m = i >> 9, k = i & 511;
        float v = x[i];
        __nv_bfloat16 hi = __float2bfloat16(v);
        float r = v - __bfloat162float(hi);
        g_Ax[m * 1024 + k] = hi;
        g_Ax[m * 1024 + 512 + k] = __float2bfloat16(r);
    }
}

// ------------------------------- prep W ------------------------------------
__global__ void k_prep_w(const float* __restrict__ Wf, const float* __restrict__ bf,
                         const float* __restrict__ Wi, const float* __restrict__ bi,
                         const float* __restrict__ Wg, const float* __restrict__ bg,
                         const float* __restrict__ Wo, const float* __restrict__ bo,
                         const float* __restrict__ Rf, const float* __restrict__ Ri,
                         const float* __restrict__ Rg, const float* __restrict__ Ro) {
    int n = blockIdx.x;          // permuted column 0..2047
    int g = n & 3, hc = n >> 2;
    const float* W = (g == 0) ? Wf : (g == 1) ? Wi : (g == 2) ? Wg : Wo;
    const float* R = (g == 0) ? Rf : (g == 1) ? Ri : (g == 2) ? Rg : Ro;
    const float* bb = (g == 0) ? bf : (g == 1) ? bi : (g == 2) ? bg : bo;

    for (int k = threadIdx.x; k < 512; k += blockDim.x) {
        float wx = W[(size_t)k * 512 + hc];
        __nv_bfloat16 hi = __float2bfloat16(wx);
        g_Bx[(size_t)n * 1024 + k] = hi;
        g_Bx[(size_t)n * 1024 + 512 + k] =
            __float2bfloat16(wx - __bfloat162float(hi));

        float wh = W[(size_t)(512 + k) * 512 + hc] + R[(size_t)k * 512 + hc];
        __nv_bfloat16 hih = __float2bfloat16(wh);
        g_Br[(size_t)n * 1024 + k] = hih;
        g_Br[(size_t)n * 1024 + 512 + k] =
            __float2bfloat16(wh - __bfloat162float(hih));
    }
    if (threadIdx.x == 0) g_b4[n] = bb[hc];

    int gt = blockIdx.x * blockDim.x + threadIdx.x;
    if (gt < 2 * BB * 1024) g_hbuf[gt] = __float2bfloat16(0.f);  // h0 = 0
    if (gt == 0) { g_cnt = 0; g_gen = 0; }
}

// --------------------------- phase B: Z0 GEMM ------------------------------
// CTA tile 128x64, 8 warps (4x2), warp tile 32x32. K chunks of 64, dbl-buffered.
#define P1_SA (128 * 72)
#define P1_SB (64 * 72)
#define P1_SMEM ((2 * P1_SA + 2 * P1_SB) * 2)

__global__ void __launch_bounds__(256) k_gemm_x() {
    extern __shared__ __nv_bfloat16 smp[];
    __nv_bfloat16* sA = smp;                // [2][128*72]
    __nv_bfloat16* sB = smp + 2 * P1_SA;    // [2][64*72]
    const int m0 = blockIdx.x * 128, n0 = blockIdx.y * 64;
    const int tid = threadIdx.x, lane = tid & 31, w = tid >> 5;
    const int wm = w & 3, wn = w >> 2;
    const int tg = lane >> 2, t4 = lane & 3;

    float acc[2][4][4];
#pragma unroll
    for (int jt = 0; jt < 4; jt++) {
        int col = n0 + wn * 32 + jt * 8 + 2 * t4;
        float b0 = g_b4[col], b1 = g_b4[col + 1];
#pragma unroll
        for (int mt = 0; mt < 2; mt++) {
            acc[mt][jt][0] = b0; acc[mt][jt][1] = b1;
            acc[mt][jt][2] = b0; acc[mt][jt][3] = b1;
        }
    }

    auto issue = [&](int cc, int buf) {
        int seg = cc >> 3, kb = (cc & 7) * 64;
        int aoff = (seg == 1) ? 512 : 0, boff = (seg == 2) ? 512 : 0;
        size_t abase = (size_t)m0 * 1024 + aoff + kb;
        for (int u = tid; u < 1024; u += 256) {
            int r = u >> 3, c8 = (u & 7) * 8;
            cp16(&sA[buf * P1_SA + r * 72 + c8], &g_Ax[abase + (size_t)r * 1024 + c8]);
        }
        size_t bbase = (size_t)n0 * 1024 + boff + kb;
        for (int u = tid; u < 512; u += 256) {
            int r = u >> 3, c8 = (u & 7) * 8;
            cp16(&sB[buf * P1_SB + r * 72 + c8], &g_Bx[bbase + (size_t)r * 1024 + c8]);
        }
        cp_commit();
    };

    issue(0, 0);
    for (int cc = 0; cc < 24; cc++) {
        int buf = cc & 1;
        if (cc < 23) {
            issue(cc + 1, buf ^ 1);
            asm volatile("cp.async.wait_group 1;\n");
        } else {
            asm volatile("cp.async.wait_group 0;\n");
        }
        __syncthreads();
#pragma unroll
        for (int kk = 0; kk < 4; kk++) {
            int ko = kk * 16;
            uint32_t a[2][4];
#pragma unroll
            for (int mt = 0; mt < 2; mt++) {
                int row = wm * 32 + mt * 16 + (lane & 15);
                int kx = ko + ((lane >> 4) << 3);
                ldsm_x4(a[mt][0], a[mt][1], a[mt][2], a[mt][3],
                        smem_u32(&sA[buf * P1_SA + row * 72 + kx]));
            }
#pragma unroll
            for (int jt = 0; jt < 4; jt++) {
                int nr = wn * 32 + jt * 8 + (lane & 7);
                int kx = ko + (((lane >> 3) & 1) << 3);
                uint32_t b0, b1;
                ldsm_x2(b0, b1, smem_u32(&sB[buf * P1_SB + nr * 72 + kx]));
                mma16816(acc[0][jt], a[0], b0, b1);
                mma16816(acc[1][jt], a[1], b0, b1);
            }
        }
        __syncthreads();
    }

#pragma unroll
    for (int mt = 0; mt < 2; mt++) {
        int row = m0 + wm * 32 + mt * 16 + tg;
#pragma unroll
        for (int jt = 0; jt < 4; jt++) {
            int col = n0 + wn * 32 + jt * 8 + 2 * t4;
            *(float2*)&g_Z0[(size_t)row * 2048 + col] =
                make_float2(acc[mt][jt][0], acc[mt][jt][1]);
            *(float2*)&g_Z0[(size_t)(row + 8) * 2048 + col] =
                make_float2(acc[mt][jt][2], acc[mt][jt][3]);
        }
    }
}

// --------------------------- phase C: recurrence ---------------------------
// 128 CTAs x 256 thr. CTA j owns permuted cols [16j,16j+16) = hidden [4j,4j+4).
// SMEM: weight slice 16x1032 + h-split A 64x1032 + Z0 dbl buf + h staging.
#define ST2 1032
#define P2_WB (16 * ST2)
#define P2_AB (64 * ST2)
#define P2_SMEM ((P2_WB + P2_AB) * 2 + (2048 + 256) * 4)
#define HX_OFF ((size_t)TT * BB * HH)

__global__ void __launch_bounds__(256) k_rnn(float* __restrict__ out, int out_size) {
    extern __shared__ __nv_bfloat16 smp[];
    __nv_bfloat16* sB = smp;                     // 16*1032
    __nv_bfloat16* sA = smp + P2_WB;             // 64*1032
    float* sZ = (float*)(smp + P2_WB + P2_AB);   // [2][1024]
    float* sH = sZ + 2048;                       // [64][4]
    const int j = blockIdx.x, n0 = j * 16;
    const int tid = threadIdx.x, lane = tid & 31, w = tid >> 5;
    const int wm = w & 3, wn = w >> 2;           // wn in [0,2)
    const int tg = lane >> 2, t4 = lane & 3;
    const bool ev = (t4 & 1) == 0;

    // resident weight slice (16 rows x 1024) for all 512 steps
    for (int u = tid; u < 16 * 128; u += 256) {
        int r = u >> 7, c8 = (u & 127) * 8;
        *(uint4*)&sB[r * ST2 + c8] = *(const uint4*)&g_Br[(size_t)(n0 + r) * 1024 + c8];
    }
    // prefetch Z0 for t=0
    {
        int r = tid >> 2, q = (tid & 3) * 4;
        cp16(&sZ[r * 16 + q], &g_Z0[(size_t)r * 2048 + n0 + q]);
    }
    cp_commit();
    asm volatile("cp.async.wait_group 0;\n");
    __syncthreads();

    const int arow = wm * 16 + (lane & 15);
    const int asel = (lane >> 4) << 3;
    const int brow = wn * 8 + (lane & 7);
    const int bsel = ((lane >> 3) & 1) << 3;

    float cst[2] = {0.f, 0.f};

    for (int t = 0; t < 512; t++) {
        int buf = t & 1, nb = buf ^ 1;

        // group 0: Z0 prefetch for t+1 (wraps harmlessly at 511)
        {
            int tz = (t + 1) & 511;
            int r = tid >> 2, q = (tid & 3) * 4;
            cp16(&sZ[nb * 1024 + r * 16 + q],
                 &g_Z0[((size_t)tz * 64 + r) * 2048 + n0 + q]);
        }
        cp_commit();
        // groups 1..4: h split, 4 chunks of 256 K-cols (64 rows x 512B each)
#pragma unroll
        for (int c = 0; c < 4; c++) {
            for (int u = tid; u < 2048; u += 256) {
                int r = u >> 5, c8 = (u & 31) * 8;
                cp16(&sA[r * ST2 + c * 256 + c8],
                     &g_hbuf[buf * 65536 + r * 1024 + c * 256 + c8]);
            }
            cp_commit();
        }

        // accumulator init = Z0 (bias folded in), from SMEM prefetch
        float acc[4];
        {
            int row = wm * 16 + tg, lc = wn * 8 + 2 * t4;
            float2 v0 = *(float2*)&sZ[buf * 1024 + row * 16 + lc];
            float2 v1 = *(float2*)&sZ[buf * 1024 + (row + 8) * 16 + lc];
            acc[0] = v0.x; acc[1] = v0.y; acc[2] = v1.x; acc[3] = v1.y;
        }

        // GEMM M=64 N=16 K'=1536, h-chunks pipelined via staged wait_group
        auto halfseg = [&](int aoff, int boff, int k0) {
#pragma unroll
            for (int kk = 0; kk < 16; kk++) {
                int ko = k0 + kk * 16;
                uint32_t a[4], b0, b1;
                ldsm_x4(a[0], a[1], a[2], a[3],
                        smem_u32(&sA[arow * ST2 + aoff + ko + asel]));
                ldsm_x2(b0, b1, smem_u32(&sB[brow * ST2 + boff + ko + bsel]));
                mma16816(acc, a, b0, b1);
            }
        };
        asm volatile("cp.async.wait_group 3;\n"); __syncthreads();
        halfseg(0, 0, 0);           // hi*hi, k 0..255   (chunk 0)
        asm volatile("cp.async.wait_group 2;\n"); __syncthreads();
        halfseg(0, 0, 256);         // hi*hi, k 256..511 (chunk 1)
        asm volatile("cp.async.wait_group 1;\n"); __syncthreads();
        halfseg(512, 0, 0);         // lo*hi, k 0..255   (chunk 2)
        asm volatile("cp.async.wait_group 0;\n"); __syncthreads();
        halfseg(512, 0, 256);       // lo*hi, k 256..511 (chunk 3)
        halfseg(0, 512, 0);         // hi*lo
        halfseg(0, 512, 256);

        // gates: even lane has (f,i), odd has (g,o) for same (rows, hc)
        {
            float r0 = __shfl_xor_sync(0xffffffffu, acc[0], 1);
            float r1 = __shfl_xor_sync(0xffffffffu, acc[1], 1);
            float r2 = __shfl_xor_sync(0xffffffffu, acc[2], 1);
            float r3 = __shfl_xor_sync(0xffffffffu, acc[3], 1);
            float zf0 = ev ? acc[0] : r0, zi0 = ev ? acc[1] : r1;
            float zg0 = ev ? r0 : acc[0], zo0 = ev ? r1 : acc[1];
            float zf1 = ev ? acc[2] : r2, zi1 = ev ? acc[3] : r3;
            float zg1 = ev ? r2 : acc[2], zo1 = ev ? r3 : acc[3];

            float c0 = sigf(zf0) * cst[0] + sigf(zi0) * tanhfast(zg0);
            float c1 = sigf(zf1) * cst[1] + sigf(zi1) * tanhfast(zg1);
            cst[0] = c0; cst[1] = c1;
            float h0 = sigf(zo0) * tanhfast(c0);
            float h1 = sigf(zo1) * tanhfast(c1);

            if (ev) {
                int b0r = wm * 16 + tg, b1r = b0r + 8;
                int hcl = 2 * wn + (t4 >> 1);
                sH[b0r * 4 + hcl] = h0;
                sH[b1r * 4 + hcl] = h1;
                if (t == 511) {
                    int hcg = 4 * j + hcl;
                    if (HX_OFF + 32768 <= (size_t)out_size) {
                        out[HX_OFF + (size_t)b0r * 512 + hcg] = h0;
                        out[HX_OFF + (size_t)b1r * 512 + hcg] = h1;
                    }
                    if (HX_OFF + 65536 <= (size_t)out_size) {
                        out[HX_OFF + 32768 + (size_t)b0r * 512 + hcg] = c0;
                        out[HX_OFF + 32768 + (size_t)b1r * 512 + hcg] = c1;
                    }
                }
            }
        }
        __syncthreads();

        // h writes: out (fp32) + hi/lo split into next h buffer
        {
            int b = tid >> 2, hc2 = tid & 3;
            float hv = sH[b * 4 + hc2];
            out[((size_t)t * 64 + b) * 512 + 4 * j + hc2] = hv;
            __nv_bfloat16 hi = __float2bfloat16(hv);
            __nv_bfloat16 lo = __float2bfloat16(hv - __bfloat162float(hi));
            g_hbuf[nb * 65536 + b * 1024 + 4 * j + hc2] = hi;
            g_hbuf[nb * 65536 + b * 1024 + 512 + 4 * j + hc2] = lo;
        }

        if (t < 511) grid_barrier();
    }
}

// ------------------------------- launch ------------------------------------
extern "C" void kernel_launch(void* const* d_in, const int* in_sizes, int n_in,
                              void* d_out, int out_size) {
    const float* x  = (const float*)d_in[0];
    const float* Wf = (const float*)d_in[1];
    const float* bf = (const float*)d_in[2];
    const float* Wi = (const float*)d_in[3];
    const float* bi = (const float*)d_in[4];
    const float* Wg = (const float*)d_in[5];
    const float* bg = (const float*)d_in[6];
    const float* Wo = (const float*)d_in[7];
    const float* bo = (const float*)d_in[8];
    const float* Rf = (const float*)d_in[9];
    const float* Ri = (const float*)d_in[10];
    const float* Rg = (const float*)d_in[11];
    const float* Ro = (const float*)d_in[12];

    cudaFuncSetAttribute(k_gemm_x, cudaFuncAttributeMaxDynamicSharedMemorySize, P1_SMEM);
    cudaFuncSetAttribute(k_rnn, cudaFuncAttributeMaxDynamicSharedMemorySize, P2_SMEM);

    k_prep_x<<<4096, 256>>>(x);
    k_prep_w<<<2048, 256>>>(Wf, bf, Wi, bi, Wg, bg, Wo, bo, Rf, Ri, Rg, Ro);
    k_gemm_x<<<dim3(256, 32), 256, P1_SMEM>>>();
    k_rnn<<<RNN_CTAS, 256, P2_SMEM>>>((float*)d_out, out_size);
}